// round 4
// baseline (speedup 1.0000x reference)
#include <cuda_runtime.h>
#include <math.h>

constexpr int   NELEM  = 8192;
constexpr int   TPB    = 128;
constexpr int   NB     = 256;            // psi buckets == blocks
constexpr int   CHUNKS = NELEM / TPB;    // 64 -> fits in a 64-bit mask
constexpr int   SHCAP  = 2048;           // window capacity (float2) = 16 KB
constexpr int   ILCAP  = 128;            // i-list capacity per bucket
constexpr float THRESH = 0.05f;
constexpr float MSEW   = 10.0f;
constexpr float LEPS   = 1e-7f;
constexpr float BINW   = 1.0f / (float)NB;

// per-block partial slots (overwritten every launch -> no init needed)
__device__ float    g_s[NB], g_sd[NB], g_sd2[NB], g_sb[NB];
__device__ int      g_c[NB];
__device__ unsigned g_done;   // zero at load; self-resets each launch

__device__ __forceinline__ float2 compute_pd(float x, float y) {
    float p = fminf(fmaxf(y, LEPS), 1.0f - LEPS);
    float l = __logf(p) - __logf(1.0f - p);
    return make_float2(y, x - l);
}

__device__ __forceinline__ float warp_sum_f(float v) {
    #pragma unroll
    for (int o = 16; o > 0; o >>= 1) v += __shfl_down_sync(0xffffffffu, v, o);
    return v;
}
__device__ __forceinline__ int warp_sum_i(int v) {
    #pragma unroll
    for (int o = 16; o > 0; o >>= 1) v += __shfl_down_sync(0xffffffffu, v, o);
    return v;
}
__device__ __forceinline__ double warp_sum_d(double v) {
    #pragma unroll
    for (int o = 16; o > 0; o >>= 1) v += __shfl_down_sync(0xffffffffu, v, o);
    return v;
}
__device__ __forceinline__ long long warp_sum_l(long long v) {
    #pragma unroll
    for (int o = 16; o > 0; o >>= 1) v += __shfl_down_sync(0xffffffffu, v, o);
    return v;
}

__global__ void __launch_bounds__(TPB)
fused(const float* __restrict__ pred, const float* __restrict__ psi,
      const int* __restrict__ flag, float* __restrict__ out)
{
    const int tid  = threadIdx.x;
    const int b    = blockIdx.x;
    const int lane = tid & 31;
    const int wrp  = tid >> 5;

    __shared__ float2 win[SHCAP];
    __shared__ short  ilist[ILCAP];
    __shared__ int    sh_wscan[TPB / 32];   // warp totals for window scan
    __shared__ int    sh_iscan[TPB / 32];   // warp totals for ilist scan
    __shared__ float  shf[TPB / 32];
    __shared__ int    shi[TPB / 32];
    __shared__ int    sh_last;

    const float lo = (float)b * BINW - (THRESH + 1e-4f);
    const float hi = (float)(b + 1) * BINW + (THRESH + 1e-4f);

    // ---------- pass 1: count survivors (window) and own-bucket elems ----------
    unsigned long long wmask = 0ull, imask = 0ull;
    int wc = 0, ic = 0;
    #pragma unroll 8
    for (int k = 0; k < CHUNKS; ++k) {
        float y = __ldg(&psi[tid + k * TPB]);          // coalesced, L2-hot
        if (y >= lo && y <= hi) {
            wmask |= (1ull << k); wc++;
            int yb = min(NB - 1, (int)(y * (float)NB));
            if (yb == b) { imask |= (1ull << k); ic++; }
        }
    }

    // ---------- block-wide exclusive scans (deterministic ordering) ----------
    int winc = wc, iinc = ic;
    #pragma unroll
    for (int o = 1; o < 32; o <<= 1) {
        int tw = __shfl_up_sync(0xffffffffu, winc, o);
        int ti = __shfl_up_sync(0xffffffffu, iinc, o);
        if (lane >= o) { winc += tw; iinc += ti; }
    }
    if (lane == 31) { sh_wscan[wrp] = winc; sh_iscan[wrp] = iinc; }
    __syncthreads();
    int wbase = 0, ibase = 0;
    #pragma unroll
    for (int w = 0; w < TPB / 32; ++w) {
        if (w < wrp) { wbase += sh_wscan[w]; ibase += sh_iscan[w]; }
    }
    int wofs = wbase + winc - wc;         // exclusive prefix
    int iofs = ibase + iinc - ic;
    int Wtot = 0, Mtot = 0;
    #pragma unroll
    for (int w = 0; w < TPB / 32; ++w) { Wtot += sh_wscan[w]; Mtot += sh_iscan[w]; }
    Wtot = min(Wtot, SHCAP);
    Mtot = min(Mtot, ILCAP);

    // ---------- pass 2: write window + ilist, accumulate moments/BCE ----------
    float sd = 0.f, sd2 = 0.f, sb = 0.f;
    {
        int wp = wofs, ip = iofs;
        unsigned long long m = wmask;
        while (m) {
            int k = __ffsll(m) - 1;
            m &= m - 1;
            int idx = tid + k * TPB;
            float y = __ldg(&psi[idx]);
            float x = __ldg(&pred[idx]);
            float2 pd = compute_pd(x, y);
            if (wp < SHCAP) win[wp] = pd;
            if ((imask >> k) & 1ull) {
                if (ip < ILCAP) ilist[ip] = (short)wp;
                ip++;
                sd  += pd.y;
                sd2 += pd.y * pd.y;
                sb  += fmaxf(x, 0.f) - x * y + log1pf(__expf(-fabsf(x)));
            }
            wp++;
        }
    }
    __syncthreads();

    // ---------- pair scan: lanes over i-elements, warps split the window ----------
    const int j0 = (Wtot * wrp)       >> 2;
    const int j1 = (Wtot * (wrp + 1)) >> 2;
    float s_acc = 0.f; int c_acc = 0;
    for (int m = lane; m < Mtot; m += 32) {
        float2 pi = win[ilist[m]];
        float yi = pi.x, di = pi.y;
        float s = 0.f; int c = 0;
        #pragma unroll 4
        for (int j = j0; j < j1; ++j) {
            float2 pj = win[j];                 // broadcast LDS.64
            float dp = yi - pj.x;
            if (fabsf(dp) < THRESH) { float dd = di - pj.y; s = fmaf(dd, dd, s); c++; }
        }
        s_acc += s; c_acc += c;
    }

    // ---------- block reduction, write this block's slots ----------
    s_acc = warp_sum_f(s_acc); c_acc = warp_sum_i(c_acc);
    sd = warp_sum_f(sd); sd2 = warp_sum_f(sd2); sb = warp_sum_f(sb);
    __shared__ float shm[3][TPB / 32];
    if (lane == 0) {
        shf[wrp] = s_acc; shi[wrp] = c_acc;
        shm[0][wrp] = sd; shm[1][wrp] = sd2; shm[2][wrp] = sb;
    }
    __syncthreads();
    if (tid == 0) {
        float s = 0.f, a = 0.f, a2 = 0.f, bb = 0.f; int c = 0;
        #pragma unroll
        for (int w = 0; w < TPB / 32; ++w) {
            s += shf[w]; c += shi[w];
            a += shm[0][w]; a2 += shm[1][w]; bb += shm[2][w];
        }
        g_s[b] = s; g_c[b] = c; g_sd[b] = a; g_sd2[b] = a2; g_sb[b] = bb;
        __threadfence();
        sh_last = (atomicAdd(&g_done, 1u) == (unsigned)(NB - 1));
        if (sh_last) __threadfence();
    }
    __syncthreads();
    if (!sh_last) return;

    // ---------- finalize (last-arriving block, deterministic order) ----------
    double ds = 0.0, ds2 = 0.0, dsb = 0.0, dsi = 0.0;
    long long ci = 0;
    for (int k = tid; k < NB; k += TPB) {
        dsi += (double)__ldcg(&g_s[k]);
        ci  += (long long)__ldcg(&g_c[k]);
        ds  += (double)__ldcg(&g_sd[k]);
        ds2 += (double)__ldcg(&g_sd2[k]);
        dsb += (double)__ldcg(&g_sb[k]);
    }
    ds = warp_sum_d(ds); ds2 = warp_sum_d(ds2); dsb = warp_sum_d(dsb);
    dsi = warp_sum_d(dsi); ci = warp_sum_l(ci);
    __shared__ double shd[4][TPB / 32];
    __shared__ long long shl[TPB / 32];
    if (lane == 0) {
        shd[0][wrp] = ds; shd[1][wrp] = ds2; shd[2][wrp] = dsb; shd[3][wrp] = dsi;
        shl[wrp] = ci;
    }
    __syncthreads();
    if (tid == 0) {
        double Sd = 0.0, Sd2 = 0.0, Sb = 0.0, Sinv = 0.0; long long Cinv = 0;
        #pragma unroll
        for (int w = 0; w < TPB / 32; ++w) {
            Sd += shd[0][w]; Sd2 += shd[1][w]; Sb += shd[2][w];
            Sinv += shd[3][w]; Cinv += shl[w];
        }
        double S_all = 2.0 * (double)NELEM * Sd2 - 2.0 * Sd * Sd;
        long long Cval = (long long)NELEM * (long long)NELEM - Cinv;
        float bce = (float)(Sb / (double)NELEM);
        int bce_only = (flag != nullptr) ? *flag : 0;
        float result;
        if (bce_only) {
            result = bce;
        } else {
            double Sval = S_all - Sinv;
            if (Sval < 0.0) Sval = 0.0;
            double mse = Sval / (double)(Cval > 0 ? Cval : 1);
            result = (Cval > 0) ? (bce + MSEW * (float)mse) : bce;
        }
        out[0] = result;
        g_done = 0u;    // self-reset for next graph replay
    }
}

extern "C" void kernel_launch(void* const* d_in, const int* in_sizes, int n_in,
                              void* d_out, int out_size) {
    const float* pred = (const float*)d_in[0];
    const float* psi  = (const float*)d_in[1];
    const int*   flag = (n_in >= 3 && in_sizes[2] >= 1) ? (const int*)d_in[2] : nullptr;
    fused<<<NB, TPB>>>(pred, psi, flag, (float*)d_out);
}

// round 5
// speedup vs baseline: 1.0178x; 1.0178x over previous
#include <cuda_runtime.h>
#include <math.h>

constexpr int   NELEM  = 8192;
constexpr int   TPB    = 128;
constexpr int   IPT    = 4;                      // i-rows per thread
constexpr int   JCHUNK = 128;                    // j-tile in shared
constexpr int   GRIDX  = NELEM / (TPB * IPT);    // 16
constexpr int   GRIDY  = NELEM / JCHUNK;         // 64
constexpr int   NBLK   = GRIDX * GRIDY;          // 1024
constexpr float THRESH = 0.05f;
constexpr float MSEW   = 10.0f;
constexpr float LEPS   = 1e-7f;

// per-block partial slots (fully overwritten every launch -> no init kernel)
__device__ float    g_ps[NBLK];
__device__ int      g_pc[NBLK];
__device__ float    g_pb[NBLK];
__device__ unsigned g_arr;      // zero at load; self-resets each launch

__device__ __forceinline__ float2 compute_pd(float x, float y) {
    // (psi, d = pred - logit(psi))
    float p = fminf(fmaxf(y, LEPS), 1.0f - LEPS);
    float l = __logf(p) - __logf(1.0f - p);
    return make_float2(y, x - l);
}

__global__ void __launch_bounds__(TPB)
fused_kernel(const float* __restrict__ pred,
             const float* __restrict__ psi,
             const int*   __restrict__ flag,
             float*       __restrict__ out) {
    __shared__ float2 sh[JCHUNK];
    __shared__ float  shs[TPB / 32];
    __shared__ int    shc[TPB / 32];
    __shared__ float  shb[TPB / 32];
    __shared__ int    sh_last;

    const int tid = threadIdx.x;
    const int bx  = blockIdx.x;          // i-block
    const int by  = blockIdx.y;          // j-chunk

    // j-tile: (psi_j, d_j) -- TPB == JCHUNK, one element per thread
    {
        int j = by * JCHUNK + tid;
        sh[tid] = compute_pd(__ldg(&pred[j]), __ldg(&psi[j]));
    }

    // my IPT i-rows: d, and precomputed threshold bounds
    float d[IPT], lo[IPT], hi[IPT], s[IPT];
    float bce = 0.0f;
    const int ibase = bx * (TPB * IPT) + tid;
    #pragma unroll
    for (int r = 0; r < IPT; ++r) {
        int i = ibase + r * TPB;
        float x = __ldg(&pred[i]);
        float y = __ldg(&psi[i]);
        float2 pd = compute_pd(x, y);
        d[r]  = pd.y;
        lo[r] = y - THRESH;
        hi[r] = y + THRESH;
        s[r]  = 0.0f;
        if (by == 0)   // BCE stripe: each i counted exactly once grid-wide
            bce += fmaxf(x, 0.0f) - x * y + log1pf(__expf(-fabsf(x)));
    }
    __syncthreads();

    float cF = 0.0f;   // count on fma pipe (r=0,1)
    int   cI = 0;      // count on alu pipe (r=2,3)

    #pragma unroll 8
    for (int k = 0; k < JCHUNK; ++k) {
        float2 pj = sh[k];                 // broadcast LDS.64, 1 per 4 pairs
        float yj = pj.x, dj = pj.y;

        bool v0 = (yj <= lo[0]) || (yj >= hi[0]);
        float dd0 = d[0] - dj;
        if (v0) { s[0] = fmaf(dd0, dd0, s[0]); cF += 1.0f; }

        bool v1 = (yj <= lo[1]) || (yj >= hi[1]);
        float dd1 = d[1] - dj;
        if (v1) { s[1] = fmaf(dd1, dd1, s[1]); cF += 1.0f; }

        bool v2 = (yj <= lo[2]) || (yj >= hi[2]);
        float dd2 = d[2] - dj;
        if (v2) { s[2] = fmaf(dd2, dd2, s[2]); cI++; }

        bool v3 = (yj <= lo[3]) || (yj >= hi[3]);
        float dd3 = d[3] - dj;
        if (v3) { s[3] = fmaf(dd3, dd3, s[3]); cI++; }
    }

    float ssum = (s[0] + s[1]) + (s[2] + s[3]);
    int   c    = cI + (int)cF;            // cF <= 256, exact in float

    // ---- block reduction (ssum, c, bce) ----
    #pragma unroll
    for (int o = 16; o > 0; o >>= 1) {
        ssum += __shfl_down_sync(0xffffffffu, ssum, o);
        c    += __shfl_down_sync(0xffffffffu, c,    o);
        bce  += __shfl_down_sync(0xffffffffu, bce,  o);
    }
    if ((tid & 31) == 0) {
        shs[tid >> 5] = ssum; shc[tid >> 5] = c; shb[tid >> 5] = bce;
    }
    __syncthreads();
    if (tid == 0) {
        float fs = 0.0f, fb = 0.0f; int fc = 0;
        #pragma unroll
        for (int w = 0; w < TPB / 32; ++w) { fs += shs[w]; fc += shc[w]; fb += shb[w]; }
        int slot = by * GRIDX + bx;
        g_ps[slot] = fs; g_pc[slot] = fc; g_pb[slot] = fb;
        __threadfence();
        sh_last = (atomicAdd(&g_arr, 1u) == (unsigned)(NBLK - 1));
        if (sh_last) __threadfence();
    }
    __syncthreads();
    if (!sh_last) return;

    // ---- finalize: last-arriving block reduces all slots (deterministic) ----
    double ds = 0.0, db = 0.0;
    long long dc = 0;
    for (int k = tid; k < NBLK; k += TPB) {
        ds += (double)__ldcg(&g_ps[k]);
        dc += (long long)__ldcg(&g_pc[k]);
        db += (double)__ldcg(&g_pb[k]);
    }
    #pragma unroll
    for (int o = 16; o > 0; o >>= 1) {
        ds += __shfl_down_sync(0xffffffffu, ds, o);
        dc += __shfl_down_sync(0xffffffffu, dc, o);
        db += __shfl_down_sync(0xffffffffu, db, o);
    }
    __shared__ double shd[2][TPB / 32];
    __shared__ long long shl[TPB / 32];
    if ((tid & 31) == 0) {
        shd[0][tid >> 5] = ds; shd[1][tid >> 5] = db; shl[tid >> 5] = dc;
    }
    __syncthreads();
    if (tid == 0) {
        double S = 0.0, B = 0.0; long long C = 0;
        #pragma unroll
        for (int w = 0; w < TPB / 32; ++w) { S += shd[0][w]; B += shd[1][w]; C += shl[w]; }
        float bce_mean = (float)(B / (double)NELEM);
        int bce_only = (flag != nullptr) ? *flag : 0;
        float result;
        if (bce_only) {
            result = bce_mean;
        } else {
            double mse = S / (double)(C > 0 ? C : 1);
            result = (C > 0) ? (bce_mean + MSEW * (float)mse) : bce_mean;
        }
        out[0] = result;
        g_arr = 0u;    // self-reset for next graph replay
    }
}

extern "C" void kernel_launch(void* const* d_in, const int* in_sizes, int n_in,
                              void* d_out, int out_size) {
    const float* pred = (const float*)d_in[0];
    const float* psi  = (const float*)d_in[1];
    const int*   flag = (n_in >= 3 && in_sizes[2] >= 1) ? (const int*)d_in[2] : nullptr;

    dim3 grid(GRIDX, GRIDY);    // 16 x 64 = 1024 blocks
    fused_kernel<<<grid, TPB>>>(pred, psi, flag, (float*)d_out);
}

// round 6
// speedup vs baseline: 1.7711x; 1.7402x over previous
#include <cuda_runtime.h>
#include <math.h>

constexpr int   NELEM  = 8192;
constexpr int   NB     = 256;            // psi buckets
constexpr int   TPA    = 1024;           // prep threads (single block)
constexpr int   EPA    = NELEM / TPA;    // 8 elems/thread
constexpr int   TPB    = 128;            // pairs threads
constexpr int   IBLK   = TPB;            // one i per thread
constexpr int   GRIDX  = NELEM / IBLK;   // 64 i-blocks
constexpr int   NSLICE = 4;              // window slices
constexpr int   NBLK   = GRIDX * NSLICE; // 256 blocks
constexpr int   SLCAP  = 1536;           // shared slice capacity (float2)
constexpr int   WMARG  = 13;             // 13/256 = 0.0508 > 0.05
constexpr float THRESH = 0.05f;
constexpr float MSEW   = 10.0f;
constexpr float LEPS   = 1e-7f;

// device scratch: fully rewritten every launch (g_arr self-resets)
__device__ float2   g_sorted[NELEM];
__device__ int      g_off[NB + 1];
__device__ double   g_momd, g_momd2, g_momb;
__device__ float    g_ps[NBLK];
__device__ int      g_pc[NBLK];
__device__ unsigned g_arr;

// ---------------- kernel A: d, moments, BCE, counting sort ----------------
__global__ void __launch_bounds__(TPA)
prep(const float* __restrict__ pred, const float* __restrict__ psi) {
    __shared__ int   hist[NB];
    __shared__ int   cur[NB];
    __shared__ float rf[3][TPA / 32];

    const int tid = threadIdx.x;
    if (tid < NB) hist[tid] = 0;
    __syncthreads();

    float yv[EPA], dv[EPA];
    int   bv[EPA];
    float sd = 0.f, sd2 = 0.f, sb = 0.f;
    #pragma unroll
    for (int r = 0; r < EPA; ++r) {
        int i = tid * EPA + r;
        float x = __ldg(&pred[i]);
        float y = __ldg(&psi[i]);
        float p = fminf(fmaxf(y, LEPS), 1.0f - LEPS);
        float d = x - __logf(__fdividef(p, 1.0f - p));
        int   b = min(NB - 1, max(0, (int)(y * (float)NB)));
        atomicAdd(&hist[b], 1);
        yv[r] = y; dv[r] = d; bv[r] = b;
        sd  += d;
        sd2 += d * d;
        sb  += fmaxf(x, 0.f) - x * y + __logf(1.0f + __expf(-fabsf(x)));
    }
    __syncthreads();

    // exclusive scan of 256 bins by warp 0 (8 bins/lane)
    if (tid < 32) {
        int v[8]; int s = 0;
        #pragma unroll
        for (int k = 0; k < 8; ++k) { v[k] = hist[tid * 8 + k]; s += v[k]; }
        int incl = s;
        #pragma unroll
        for (int o = 1; o < 32; o <<= 1) {
            int t = __shfl_up_sync(0xffffffffu, incl, o);
            if (tid >= o) incl += t;
        }
        int run = incl - s;
        #pragma unroll
        for (int k = 0; k < 8; ++k) {
            cur[tid * 8 + k]   = run;
            g_off[tid * 8 + k] = run;
            run += v[k];
        }
        if (tid == 31) g_off[NB] = run;
    }
    __syncthreads();

    // scatter into bucket order
    #pragma unroll
    for (int r = 0; r < EPA; ++r) {
        int pos = atomicAdd(&cur[bv[r]], 1);
        g_sorted[pos] = make_float2(yv[r], dv[r]);
    }

    // moments reduction (warp shuffle -> 32 warp slots -> double)
    #pragma unroll
    for (int o = 16; o > 0; o >>= 1) {
        sd  += __shfl_down_sync(0xffffffffu, sd,  o);
        sd2 += __shfl_down_sync(0xffffffffu, sd2, o);
        sb  += __shfl_down_sync(0xffffffffu, sb,  o);
    }
    if ((tid & 31) == 0) {
        rf[0][tid >> 5] = sd; rf[1][tid >> 5] = sd2; rf[2][tid >> 5] = sb;
    }
    __syncthreads();
    if (tid < 32) {
        double a = (double)rf[0][tid];
        double b = (double)rf[1][tid];
        double c = (double)rf[2][tid];
        #pragma unroll
        for (int o = 16; o > 0; o >>= 1) {
            a += __shfl_down_sync(0xffffffffu, a, o);
            b += __shfl_down_sync(0xffffffffu, b, o);
            c += __shfl_down_sync(0xffffffffu, c, o);
        }
        if (tid == 0) { g_momd = a; g_momd2 = b; g_momb = c; }
    }
}

// ---------------- kernel B: invalid-pair window scan + finalize ----------------
__global__ void __launch_bounds__(TPB)
pairs(const int* __restrict__ flag, float* __restrict__ out) {
    __shared__ float2 win[SLCAP];
    __shared__ float  shs[TPB / 32];
    __shared__ int    shc[TPB / 32];
    __shared__ int    sh_last;

    const int tid = threadIdx.x;
    const int bx  = blockIdx.x;
    const int sy  = blockIdx.y;
    const int p0  = bx * IBLK;

    // window bucket range from block's (bucket-sorted) psi span
    const float yfirst = g_sorted[p0].x;
    const float ylast  = g_sorted[p0 + IBLK - 1].x;
    const int bf = max(0,  (int)(yfirst * (float)NB) - WMARG);
    const int bl = min(NB, (int)(ylast  * (float)NB) + WMARG + 1);
    const int wlo  = g_off[bf];
    const int whi  = g_off[bl];
    const int wlen = whi - wlo;
    const int s0   = wlo + (wlen * sy)       / NSLICE;
    const int s1   = wlo + (wlen * (sy + 1)) / NSLICE;
    const int slen = s1 - s0;
    const int sl   = min(slen, SLCAP);

    for (int k = tid; k < sl; k += TPB) win[k] = g_sorted[s0 + k];
    __syncthreads();

    const float2 pi = g_sorted[p0 + tid];
    const float yi = pi.x, di = pi.y;

    float s = 0.f; int c = 0;
    #pragma unroll 4
    for (int k = 0; k < sl; ++k) {
        float2 pj = win[k];                    // broadcast LDS.64
        float dp = yi - pj.x;
        float dd = di - pj.y;
        if (fabsf(dp) < THRESH) { s = fmaf(dd, dd, s); c++; }
    }
    for (int k = sl; k < slen; ++k) {          // overflow fallback (normally empty)
        float2 pj = g_sorted[s0 + k];
        float dp = yi - pj.x;
        float dd = di - pj.y;
        if (fabsf(dp) < THRESH) { s = fmaf(dd, dd, s); c++; }
    }

    // block reduction -> slot
    #pragma unroll
    for (int o = 16; o > 0; o >>= 1) {
        s += __shfl_down_sync(0xffffffffu, s, o);
        c += __shfl_down_sync(0xffffffffu, c, o);
    }
    if ((tid & 31) == 0) { shs[tid >> 5] = s; shc[tid >> 5] = c; }
    __syncthreads();
    if (tid == 0) {
        float fs = 0.f; int fc = 0;
        #pragma unroll
        for (int w = 0; w < TPB / 32; ++w) { fs += shs[w]; fc += shc[w]; }
        int slot = sy * GRIDX + bx;
        g_ps[slot] = fs; g_pc[slot] = fc;
        __threadfence();
        sh_last = (atomicAdd(&g_arr, 1u) == (unsigned)(NBLK - 1));
        if (sh_last) __threadfence();
    }
    __syncthreads();
    if (!sh_last) return;

    // finalize in last-arriving block
    double dsi = 0.0; long long ci = 0;
    for (int k = tid; k < NBLK; k += TPB) {
        dsi += (double)__ldcg(&g_ps[k]);
        ci  += (long long)__ldcg(&g_pc[k]);
    }
    #pragma unroll
    for (int o = 16; o > 0; o >>= 1) {
        dsi += __shfl_down_sync(0xffffffffu, dsi, o);
        ci  += __shfl_down_sync(0xffffffffu, ci,  o);
    }
    __shared__ double    shd[TPB / 32];
    __shared__ long long shl[TPB / 32];
    if ((tid & 31) == 0) { shd[tid >> 5] = dsi; shl[tid >> 5] = ci; }
    __syncthreads();
    if (tid == 0) {
        double Sinv = 0.0; long long Cinv = 0;
        #pragma unroll
        for (int w = 0; w < TPB / 32; ++w) { Sinv += shd[w]; Cinv += shl[w]; }
        double Sd = g_momd, Sd2 = g_momd2, Sb = g_momb;
        double S_all = 2.0 * (double)NELEM * Sd2 - 2.0 * Sd * Sd;
        long long Cval = (long long)NELEM * (long long)NELEM - Cinv;
        float bce = (float)(Sb / (double)NELEM);
        int bce_only = (flag != nullptr) ? *flag : 0;
        float result;
        if (bce_only) {
            result = bce;
        } else {
            double Sval = S_all - Sinv;
            if (Sval < 0.0) Sval = 0.0;
            double mse = Sval / (double)(Cval > 0 ? Cval : 1);
            result = (Cval > 0) ? (bce + MSEW * (float)mse) : bce;
        }
        out[0] = result;
        g_arr = 0u;   // self-reset for next graph replay
    }
}

extern "C" void kernel_launch(void* const* d_in, const int* in_sizes, int n_in,
                              void* d_out, int out_size) {
    const float* pred = (const float*)d_in[0];
    const float* psi  = (const float*)d_in[1];
    const int*   flag = (n_in >= 3 && in_sizes[2] >= 1) ? (const int*)d_in[2] : nullptr;

    prep<<<1, TPA>>>(pred, psi);
    pairs<<<dim3(GRIDX, NSLICE), TPB>>>(flag, (float*)d_out);
}